// round 7
// baseline (speedup 1.0000x reference)
#include <cuda_runtime.h>
#include <cuda_bf16.h>
#include <math.h>
#include <stdint.h>

#define NCAM 6
#define CF   128
#define HF   32
#define WF   88
#define PP   4
#define HB   160
#define WB   160
#define QQ   (HB*WB)          // 25600
#define MROWS QQ
#define MR2   (QQ*PP)         // 102400 pe rows
#define KDIM 512
#define MIDW 256
#define EDIM 128
#define IMGW 704.0f
#define IMGH 256.0f
#define EPSF 1e-5f

// ---- scratch ----
__device__ float g_fmap[NCAM*HF*WF*CF];
__device__ float g_x   [MROWS*KDIM];       // sampled features fp32 (pre-PE)
__device__ float g_y1  [MROWS*KDIM];
__device__ float g_y2  [MROWS*EDIM];
__device__ float g_mean1[KDIM];
__device__ float g_inv1 [KDIM];
__device__ float g_mean2[EDIM];
__device__ float g_inv2 [EDIM];

__device__ __align__(16) __nv_bfloat16 g_xh[MROWS*KDIM], g_xl[MROWS*KDIM];
__device__ __align__(16) __nv_bfloat16 g_c1h[KDIM*KDIM], g_c1l[KDIM*KDIM];
__device__ __align__(16) __nv_bfloat16 g_c2h[EDIM*KDIM], g_c2l[EDIM*KDIM];
__device__ __align__(16) __nv_bfloat16 g_c3h[EDIM*EDIM], g_c3l[EDIM*EDIM];
__device__ __align__(16) __nv_bfloat16 g_w2h[MIDW*MIDW], g_w2l[MIDW*MIDW];
__device__ __align__(16) __nv_bfloat16 g_w3h[EDIM*MIDW], g_w3l[EDIM*MIDW];

__device__ __forceinline__ void split2(float v, __nv_bfloat16 &h, __nv_bfloat16 &l){
    h = __float2bfloat16(v);
    l = __float2bfloat16(v - __bfloat162float(h));
}
__device__ __forceinline__ float gelu_f(float x){
    return 0.5f * x * (1.0f + erff(x * 0.70710678118654752440f));
}
__device__ __forceinline__ void ldsm4(uint32_t* r, uint32_t addr){
    asm volatile("ldmatrix.sync.aligned.m8n8.x4.shared.b16 {%0,%1,%2,%3}, [%4];"
        : "=r"(r[0]),"=r"(r[1]),"=r"(r[2]),"=r"(r[3]) : "r"(addr));
}
__device__ __forceinline__ void mma16816(float* d, const uint32_t* a, const uint32_t* b){
    asm volatile("mma.sync.aligned.m16n8k16.row.col.f32.bf16.bf16.f32 "
        "{%0,%1,%2,%3}, {%4,%5,%6,%7}, {%8,%9}, {%0,%1,%2,%3};"
        : "+f"(d[0]),"+f"(d[1]),"+f"(d[2]),"+f"(d[3])
        : "r"(a[0]),"r"(a[1]),"r"(a[2]),"r"(a[3]), "r"(b[0]),"r"(b[1]));
}

// ============================================================
// 0) transpose feat [N,C,H,W] -> [N,H,W,C]
// ============================================================
__global__ void k_transpose(const float* __restrict__ feat){
    int idx = blockIdx.x*blockDim.x + threadIdx.x;
    const int total = NCAM*HF*WF*CF;
    if (idx >= total) return;
    int c = idx & (CF-1);
    int rest = idx >> 7;
    int w = rest % WF;
    rest /= WF;
    int h = rest % HF;
    int n = rest / HF;
    g_fmap[idx] = feat[((n*CF + c)*HF + h)*WF + w];
}

// ============================================================
// 1) projection + bilinear sampling -> g_x fp32
// ============================================================
__global__ void k_sample(const float* __restrict__ bev, const float* __restrict__ l2i){
    __shared__ float sL[NCAM*16];
    int tid = threadIdx.x;
    if (tid < NCAM*16) sL[tid] = l2i[tid];
    __syncthreads();
    int gw   = (blockIdx.x*blockDim.x + tid) >> 5;
    int lane = tid & 31;
    if (gw >= QQ*PP) return;
    int q = gw >> 2, p = gw & 3;
    const float* bp = bev + (p*QQ + q)*3;
    float rx = bp[0]*100.0f - 50.0f;
    float ry = bp[1]*100.0f - 50.0f;
    float rz = bp[2]*8.0f   - 4.0f;
    float4 acc = make_float4(0.f,0.f,0.f,0.f);
    #pragma unroll
    for (int n=0;n<NCAM;n++){
        const float* L = sL + n*16;
        float c0 = L[0]*rx + L[1]*ry + L[2]*rz  + L[3];
        float c1 = L[4]*rx + L[5]*ry + L[6]*rz  + L[7];
        float hm = L[8]*rx + L[9]*ry + L[10]*rz + L[11];
        float z  = fmaxf(hm, EPSF);
        float u  = (c0 / z) / IMGW;
        float v  = (c1 / z) / IMGH;
        if (!(hm > EPSF && u > 0.f && u < 1.f && v > 0.f && v < 1.f)) continue;
        float x = u*(float)WF - 0.5f;
        float y = v*(float)HF - 0.5f;
        float x0f = floorf(x), y0f = floorf(y);
        float dx = x - x0f,    dy = y - y0f;
        int x0 = (int)x0f,     y0 = (int)y0f;
        float ws[4] = {(1.f-dx)*(1.f-dy), dx*(1.f-dy), (1.f-dx)*dy, dx*dy};
        int   xs[4] = {x0, x0+1, x0,   x0+1};
        int   ys[4] = {y0, y0,   y0+1, y0+1};
        const float* base = g_fmap + (size_t)n*HF*WF*CF;
        #pragma unroll
        for (int cr=0; cr<4; cr++){
            int xi = xs[cr], yi = ys[cr];
            if (xi >= 0 && xi < WF && yi >= 0 && yi < HF){
                float4 vq = reinterpret_cast<const float4*>(base + (yi*WF + xi)*CF)[lane];
                float wq = ws[cr];
                acc.x = fmaf(wq, vq.x, acc.x);
                acc.y = fmaf(wq, vq.y, acc.y);
                acc.z = fmaf(wq, vq.z, acc.z);
                acc.w = fmaf(wq, vq.w, acc.w);
            }
        }
    }
    reinterpret_cast<float4*>(g_x)[gw*32 + lane] = acc;
}

// ============================================================
// weight split kernels
// ============================================================
__global__ void k_wsplit(const float* __restrict__ s, __nv_bfloat16* __restrict__ h,
                         __nv_bfloat16* __restrict__ l, int n){
    int i = blockIdx.x*256 + threadIdx.x;
    if (i < n) split2(s[i], h[i], l[i]);
}
__global__ void k_wsplitT(const float* __restrict__ s, __nv_bfloat16* __restrict__ h,
                          __nv_bfloat16* __restrict__ l, int Nn){
    int i = blockIdx.x*256 + threadIdx.x;   // i = n*256 + k
    int k = i & 255, n_ = i >> 8;
    if (n_ < Nn) split2(s[k*Nn + n_], h[i], l[i]);
}

// ============================================================
// 2) fully fused PE: layer1 on-the-fly, layer2+3 MMA in smem.
//    Block = 128 qp rows, 256 threads (8 warps, 2m x 4n).
//    Output: (g_x + PE) split to g_xh/g_xl.
// ============================================================
#define SLDK 24    // stage row stride (16 k + 8 pad), bf16 elems
#define HLDK 264   // h2 row stride (256 + 8), bf16 elems

// smem byte offsets
#define PE_REFS   0                         // float[128*3]       1536
#define PE_W1S    1536                      // float[768]         3072
#define PE_B1S    4608                      // float[256]         1024
#define PE_SAH    5632                      // bf16[128*SLDK]     6144
#define PE_SAL    11776
#define PE_SWH    17920
#define PE_SWL    24064
#define PE_H2H    30208                     // bf16[128*HLDK]     67584
#define PE_H2L    97792
#define PE_SMEM   165376

__global__ __launch_bounds__(256)
void k_pefused(const float* __restrict__ bev,
               const float* __restrict__ w1, const float* __restrict__ b1,
               const __nv_bfloat16* __restrict__ w2h, const __nv_bfloat16* __restrict__ w2l,
               const float* __restrict__ b2,
               const __nv_bfloat16* __restrict__ w3h, const __nv_bfloat16* __restrict__ w3l,
               const float* __restrict__ b3)
{
    extern __shared__ char sm[];
    float* refS = (float*)(sm + PE_REFS);
    float* w1s  = (float*)(sm + PE_W1S);
    float* b1s  = (float*)(sm + PE_B1S);
    __nv_bfloat16* sAh = (__nv_bfloat16*)(sm + PE_SAH);
    __nv_bfloat16* sAl = (__nv_bfloat16*)(sm + PE_SAL);
    __nv_bfloat16* sWh = (__nv_bfloat16*)(sm + PE_SWH);
    __nv_bfloat16* sWl = (__nv_bfloat16*)(sm + PE_SWL);
    __nv_bfloat16* h2h = (__nv_bfloat16*)(sm + PE_H2H);
    __nv_bfloat16* h2l = (__nv_bfloat16*)(sm + PE_H2L);

    const int tid = threadIdx.x;
    const int row0 = blockIdx.x * 128;
    const int lane = tid & 31, warp = tid >> 5;
    const int wm = warp & 1, wn = warp >> 1;

    // init: ref coords + layer1 weights
    for (int i = tid; i < 384; i += 256){
        int r = i / 3, d = i - r*3;
        int qp = row0 + r;
        int q = qp >> 2, p = qp & 3;
        refS[i] = bev[(p*QQ + q)*3 + d];
    }
    for (int i = tid; i < 768; i += 256) w1s[i] = w1[i];
    b1s[tid & 255] = b1[tid & 255];
    __syncthreads();

    const uint32_t bAh = (uint32_t)__cvta_generic_to_shared(sAh);
    const uint32_t bAl = (uint32_t)__cvta_generic_to_shared(sAl);
    const uint32_t bWh = (uint32_t)__cvta_generic_to_shared(sWh);
    const uint32_t bWl = (uint32_t)__cvta_generic_to_shared(sWl);
    const uint32_t bH2h = (uint32_t)__cvta_generic_to_shared(h2h);
    const uint32_t bH2l = (uint32_t)__cvta_generic_to_shared(h2l);

    const int sr = tid >> 1;           // 0..127 (stage row)
    const int sc = (tid & 1) * 8;      // 0 or 8

    const int aoff = (wm*64 + (lane & 15))*SLDK + (lane >> 4)*8;
    const int woff = (wn*32 + ((lane >> 4) << 3) + (lane & 7))*SLDK + ((lane >> 3) & 1)*8;
    const int h2off_row = wm*64 + (lane & 15);

    float acc[4][4][4];

    // ---------------- layer 2: two N-halves of 128 ----------------
    #pragma unroll 1
    for (int half = 0; half < 2; half++){
        #pragma unroll
        for(int i=0;i<4;i++)
            #pragma unroll
            for(int j=0;j<4;j++)
                #pragma unroll
                for(int v=0;v<4;v++) acc[i][j][v]=0.f;

        #pragma unroll 1
        for (int k0 = 0; k0 < MIDW; k0 += 16){
            // stage h1 chunk: h1[sr][sc..sc+7] = relu(layer1)
            {
                float a0 = refS[sr*3+0], a1 = refS[sr*3+1], a2 = refS[sr*3+2];
                __nv_bfloat16 hh[8], ll[8];
                #pragma unroll
                for (int i=0;i<8;i++){
                    int j = k0 + sc + i;
                    float h = b1s[j] + a0*w1s[j] + a1*w1s[256+j] + a2*w1s[512+j];
                    h = fmaxf(h, 0.f);
                    split2(h, hh[i], ll[i]);
                }
                *(uint4*)(sAh + sr*SLDK + sc) = *(uint4*)hh;
                *(uint4*)(sAl + sr*SLDK + sc) = *(uint4*)ll;
            }
            // stage W2 chunk: rows half*128+sr, cols k0+sc..+7
            {
                size_t go = (size_t)(half*128 + sr)*MIDW + k0 + sc;
                *(uint4*)(sWh + sr*SLDK + sc) = *(const uint4*)(w2h + go);
                *(uint4*)(sWl + sr*SLDK + sc) = *(const uint4*)(w2l + go);
            }
            __syncthreads();
            {
                uint32_t bh[2][4], bl[2][4];
                #pragma unroll
                for (int np=0; np<2; np++){
                    uint32_t off = (uint32_t)(woff + np*16*SLDK)*2;
                    ldsm4(bh[np], bWh + off);
                    ldsm4(bl[np], bWl + off);
                }
                #pragma unroll
                for (int mf=0; mf<4; mf++){
                    uint32_t off = (uint32_t)(aoff + mf*16*SLDK)*2;
                    uint32_t ah[4], al[4];
                    ldsm4(ah, bAh + off);
                    ldsm4(al, bAl + off);
                    #pragma unroll
                    for (int nf=0; nf<4; nf++){
                        const uint32_t* BH = &bh[nf>>1][(nf&1)*2];
                        const uint32_t* BL = &bl[nf>>1][(nf&1)*2];
                        mma16816(acc[mf][nf], ah, BH);
                        mma16816(acc[mf][nf], ah, BL);
                        mma16816(acc[mf][nf], al, BH);
                    }
                }
            }
            __syncthreads();
        }
        // epilogue half -> h2 smem (relu + split)
        {
            const int er = wm*64 + (lane>>2);
            const int ec = half*128 + wn*32 + (lane&3)*2;
            #pragma unroll
            for (int mf=0; mf<4; mf++){
                #pragma unroll
                for (int nf=0; nf<4; nf++){
                    int c = ec + nf*8;
                    float b0v = b2[c], b1v = b2[c+1];
                    #pragma unroll
                    for (int hh2=0; hh2<2; hh2++){
                        int r = er + mf*16 + hh2*8;
                        float v0 = fmaxf(acc[mf][nf][hh2*2+0] + b0v, 0.f);
                        float v1 = fmaxf(acc[mf][nf][hh2*2+1] + b1v, 0.f);
                        __nv_bfloat16 h0,l0,h1,l1;
                        split2(v0,h0,l0); split2(v1,h1,l1);
                        *(__nv_bfloat162*)(h2h + r*HLDK + c) = __halves2bfloat162(h0,h1);
                        *(__nv_bfloat162*)(h2l + r*HLDK + c) = __halves2bfloat162(l0,l1);
                    }
                }
            }
        }
        __syncthreads();
    }

    // ---------------- layer 3: K=256 from smem h2 ----------------
    #pragma unroll
    for(int i=0;i<4;i++)
        #pragma unroll
        for(int j=0;j<4;j++)
            #pragma unroll
            for(int v=0;v<4;v++) acc[i][j][v]=0.f;

    #pragma unroll 1
    for (int k0 = 0; k0 < MIDW; k0 += 16){
        // stage W3 chunk: rows sr (128 n), cols k0+sc
        {
            size_t go = (size_t)sr*MIDW + k0 + sc;
            *(uint4*)(sWh + sr*SLDK + sc) = *(const uint4*)(w3h + go);
            *(uint4*)(sWl + sr*SLDK + sc) = *(const uint4*)(w3l + go);
        }
        __syncthreads();
        {
            uint32_t bh[2][4], bl[2][4];
            #pragma unroll
            for (int np=0; np<2; np++){
                uint32_t off = (uint32_t)(woff + np*16*SLDK)*2;
                ldsm4(bh[np], bWh + off);
                ldsm4(bl[np], bWl + off);
            }
            #pragma unroll
            for (int mf=0; mf<4; mf++){
                uint32_t off = (uint32_t)((h2off_row + mf*16)*HLDK + k0 + (lane>>4)*8)*2;
                uint32_t ah[4], al[4];
                ldsm4(ah, bH2h + off);
                ldsm4(al, bH2l + off);
                #pragma unroll
                for (int nf=0; nf<4; nf++){
                    const uint32_t* BH = &bh[nf>>1][(nf&1)*2];
                    const uint32_t* BL = &bl[nf>>1][(nf&1)*2];
                    mma16816(acc[mf][nf], ah, BH);
                    mma16816(acc[mf][nf], ah, BL);
                    mma16816(acc[mf][nf], al, BH);
                }
            }
        }
        __syncthreads();
    }

    // final epilogue: (g_x + pe + b3) -> split to g_xh/g_xl
    {
        const int er = wm*64 + (lane>>2);
        const int ec = wn*32 + (lane&3)*2;
        #pragma unroll
        for (int mf=0; mf<4; mf++){
            #pragma unroll
            for (int nf=0; nf<4; nf++){
                int c = ec + nf*8;
                float b0v = b3[c], b1v = b3[c+1];
                #pragma unroll
                for (int hh2=0; hh2<2; hh2++){
                    int r = row0 + er + mf*16 + hh2*8;
                    float2 gx = *(float2*)(g_x + (size_t)r*EDIM + c);
                    float v0 = acc[mf][nf][hh2*2+0] + b0v + gx.x;
                    float v1 = acc[mf][nf][hh2*2+1] + b1v + gx.y;
                    __nv_bfloat16 h0,l0,h1,l1;
                    split2(v0,h0,l0); split2(v1,h1,l1);
                    *(__nv_bfloat162*)(g_xh + (size_t)r*EDIM + c) = __halves2bfloat162(h0,h1);
                    *(__nv_bfloat162*)(g_xl + (size_t)r*EDIM + c) = __halves2bfloat162(l0,l1);
                }
            }
        }
    }
}

// ============================================================
// 3) bf16x3 tensor-core GEMM (128x128 block, 8 warps).
//    AMODE 0: A pre-split (Ah/Al). AMODE 1: A fp32 + fused
//    instance-norm + gelu + split on stage.
//    EPI 0: fp32 [m][N].  EPI 3: fp32 transposed [n][MROWS].
// ============================================================
#define LDK 40

template<int K,int N,int EPI,int AMODE>
__global__ __launch_bounds__(256)
void k_mma(const __nv_bfloat16* __restrict__ Ah, const __nv_bfloat16* __restrict__ Al,
           const float* __restrict__ Afp, const float* __restrict__ mean,
           const float* __restrict__ inv,
           const __nv_bfloat16* __restrict__ Wh, const __nv_bfloat16* __restrict__ Wl,
           const float* __restrict__ bias, float* __restrict__ outF)
{
    __shared__ __align__(16) __nv_bfloat16 sAh[128*LDK], sAl[128*LDK];
    __shared__ __align__(16) __nv_bfloat16 sWh[128*LDK], sWl[128*LDK];
    const int tid = threadIdx.x;
    const int m0 = blockIdx.x*128, n0 = blockIdx.y*128;
    const int lane = tid & 31, warp = tid >> 5;
    const int wm = warp & 1, wn = warp >> 1;

    float acc[4][4][4];
    #pragma unroll
    for(int i=0;i<4;i++)
        #pragma unroll
        for(int j=0;j<4;j++)
            #pragma unroll
            for(int v=0;v<4;v++) acc[i][j][v]=0.f;

    const uint32_t bAh = (uint32_t)__cvta_generic_to_shared(sAh);
    const uint32_t bAl = (uint32_t)__cvta_generic_to_shared(sAl);
    const uint32_t bWh = (uint32_t)__cvta_generic_to_shared(sWh);
    const uint32_t bWl = (uint32_t)__cvta_generic_to_shared(sWl);

    const int gr = tid >> 2;
    const int gc = (tid & 3) * 8;

    const int aoff0 = (wm*64 + (lane & 15))*LDK + (lane >> 4)*8;
    const int woff0 = (wn*32 + ((lane >> 4) << 3) + (lane & 7))*LDK + ((lane >> 3) & 1)*8;

    for (int k0 = 0; k0 < K; k0 += 32){
        #pragma unroll
        for (int it=0; it<2; it++){
            int r = gr + it*64;
            if (AMODE == 0){
                const size_t ga = (size_t)(m0+r)*K + k0 + gc;
                *(uint4*)(sAh + r*LDK + gc) = *(const uint4*)(Ah + ga);
                *(uint4*)(sAl + r*LDK + gc) = *(const uint4*)(Al + ga);
            } else {
                const float* src = Afp + (size_t)(m0+r)*K + k0 + gc;
                float4 f0 = *(const float4*)(src);
                float4 f1 = *(const float4*)(src + 4);
                float vv[8] = {f0.x,f0.y,f0.z,f0.w,f1.x,f1.y,f1.z,f1.w};
                __nv_bfloat16 hh[8], ll[8];
                #pragma unroll
                for (int i=0;i<8;i++){
                    int kc = k0 + gc + i;
                    float v = (vv[i] - mean[kc]) * inv[kc];
                    v = gelu_f(v);
                    split2(v, hh[i], ll[i]);
                }
                *(uint4*)(sAh + r*LDK + gc) = *(uint4*)hh;
                *(uint4*)(sAl + r*LDK + gc) = *(uint4*)ll;
            }
            const size_t gb = (size_t)(n0+r)*K + k0 + gc;
            *(uint4*)(sWh + r*LDK + gc) = *(const uint4*)(Wh + gb);
            *(uint4*)(sWl + r*LDK + gc) = *(const uint4*)(Wl + gb);
        }
        __syncthreads();
        #pragma unroll
        for (int kk=0; kk<2; kk++){
            uint32_t bh[2][4], bl[2][4];
            #pragma unroll
            for (int np=0; np<2; np++){
                uint32_t off = (uint32_t)(woff0 + np*16*LDK + kk*16)*2;
                ldsm4(bh[np], bWh + off);
                ldsm4(bl[np], bWl + off);
            }
            #pragma unroll
            for (int mf=0; mf<4; mf++){
                uint32_t off = (uint32_t)(aoff0 + mf*16*LDK + kk*16)*2;
                uint32_t ah[4], al[4];
                ldsm4(ah, bAh + off);
                ldsm4(al, bAl + off);
                #pragma unroll
                for (int nf=0; nf<4; nf++){
                    const uint32_t* BH = &bh[nf>>1][(nf&1)*2];
                    const uint32_t* BL = &bl[nf>>1][(nf&1)*2];
                    mma16816(acc[mf][nf], ah, BH);
                    mma16816(acc[mf][nf], ah, BL);
                    mma16816(acc[mf][nf], al, BH);
                }
            }
        }
        __syncthreads();
    }

    const int er = m0 + wm*64 + (lane>>2);
    const int ec = n0 + wn*32 + (lane&3)*2;
    #pragma unroll
    for (int mf=0; mf<4; mf++){
        #pragma unroll
        for (int nf=0; nf<4; nf++){
            int c = ec + nf*8;
            float b0v = bias[c], b1v = bias[c+1];
            #pragma unroll
            for (int hh=0; hh<2; hh++){
                int r = er + mf*16 + hh*8;
                float v0 = acc[mf][nf][hh*2+0] + b0v;
                float v1 = acc[mf][nf][hh*2+1] + b1v;
                if (EPI == 0){
                    *(float2*)(outF + (size_t)r*N + c) = make_float2(v0, v1);
                } else {
                    outF[(size_t)c*MROWS + r]     = v0;
                    outF[(size_t)(c+1)*MROWS + r] = v1;
                }
            }
        }
    }
}

// ============================================================
// 4) InstanceNorm stats
// ============================================================
template<int NCH>
__device__ __forceinline__ void stats_body(const float* __restrict__ Y,
                                           float* __restrict__ meanO, float* __restrict__ invO){
    int tid = threadIdx.x;
    int c   = blockIdx.x*8 + (tid & 7);
    int ml  = tid >> 3;
    float s = 0.f, s2 = 0.f;
    for (int m = ml; m < MROWS; m += 32){
        float v = Y[(size_t)m*NCH + c];
        s  += v;
        s2 = fmaf(v, v, s2);
    }
    __shared__ float ss[256], ss2[256];
    ss[tid] = s; ss2[tid] = s2;
    __syncthreads();
    #pragma unroll
    for (int st=128; st>=8; st>>=1){
        if (tid < st){ ss[tid]+=ss[tid+st]; ss2[tid]+=ss2[tid+st]; }
        __syncthreads();
    }
    if (tid < 8){
        float mean = ss[tid] / (float)MROWS;
        float var  = ss2[tid] / (float)MROWS - mean*mean;
        meanO[c] = mean;
        invO[c]  = rsqrtf(var + 1e-5f);
    }
}
__global__ void k_stats1(){ stats_body<KDIM>(g_y1, g_mean1, g_inv1); }
__global__ void k_stats2(){ stats_body<EDIM>(g_y2, g_mean2, g_inv2); }

// ============================================================
// host entry
// ============================================================
extern "C" void kernel_launch(void* const* d_in, const int* in_sizes, int n_in,
                              void* d_out, int out_size){
    const float* feat = (const float*)d_in[0];
    const float* l2i  = (const float*)d_in[1];
    const float* bev  = (const float*)d_in[2];
    const float* w1   = (const float*)d_in[3];
    const float* b1   = (const float*)d_in[4];
    const float* w2   = (const float*)d_in[5];
    const float* b2   = (const float*)d_in[6];
    const float* w3   = (const float*)d_in[7];
    const float* b3   = (const float*)d_in[8];
    const float* c1w  = (const float*)d_in[9];
    const float* c1b  = (const float*)d_in[10];
    const float* c2w  = (const float*)d_in[11];
    const float* c2b  = (const float*)d_in[12];
    const float* c3w  = (const float*)d_in[13];
    const float* c3b  = (const float*)d_in[14];
    float* out = (float*)d_out;

    __nv_bfloat16 *xh, *xl, *c1h, *c1l, *c2h, *c2l, *c3h, *c3l, *w2h, *w2l, *w3h, *w3l;
    float *y1p, *y2p, *m1, *i1, *m2, *i2;
    cudaGetSymbolAddress((void**)&xh,  g_xh ); cudaGetSymbolAddress((void**)&xl,  g_xl );
    cudaGetSymbolAddress((void**)&c1h, g_c1h); cudaGetSymbolAddress((void**)&c1l, g_c1l);
    cudaGetSymbolAddress((void**)&c2h, g_c2h); cudaGetSymbolAddress((void**)&c2l, g_c2l);
    cudaGetSymbolAddress((void**)&c3h, g_c3h); cudaGetSymbolAddress((void**)&c3l, g_c3l);
    cudaGetSymbolAddress((void**)&w2h, g_w2h); cudaGetSymbolAddress((void**)&w2l, g_w2l);
    cudaGetSymbolAddress((void**)&w3h, g_w3h); cudaGetSymbolAddress((void**)&w3l, g_w3l);
    cudaGetSymbolAddress((void**)&y1p, g_y1);  cudaGetSymbolAddress((void**)&y2p, g_y2);
    cudaGetSymbolAddress((void**)&m1, g_mean1); cudaGetSymbolAddress((void**)&i1, g_inv1);
    cudaGetSymbolAddress((void**)&m2, g_mean2); cudaGetSymbolAddress((void**)&i2, g_inv2);

    static int smem_set = 0;
    if (!smem_set){
        cudaFuncSetAttribute(k_pefused, cudaFuncAttributeMaxDynamicSharedMemorySize, PE_SMEM);
        smem_set = 1;
    }

    // launch order chosen so ncu (-s 5) profiles k_sample
    k_transpose<<<(NCAM*HF*WF*CF + 255)/256, 256>>>(feat);              // 0
    k_wsplit <<<(KDIM*KDIM+255)/256, 256>>>(c1w, c1h, c1l, KDIM*KDIM); // 1
    k_wsplit <<<(EDIM*KDIM+255)/256, 256>>>(c2w, c2h, c2l, EDIM*KDIM); // 2
    k_wsplit <<<(EDIM*EDIM+255)/256, 256>>>(c3w, c3h, c3l, EDIM*EDIM); // 3
    k_wsplitT<<<(MIDW*MIDW+255)/256, 256>>>(w2, w2h, w2l, MIDW);       // 4
    k_sample <<<(QQ*PP)/8, 256>>>(bev, l2i);                           // 5 <- profiled
    k_wsplitT<<<(EDIM*MIDW+255)/256, 256>>>(w3, w3h, w3l, EDIM);       // 6

    k_pefused<<<MR2/128, 256, PE_SMEM>>>(bev, w1, b1, w2h, w2l, b2, w3h, w3l, b3);

    k_mma<KDIM,KDIM,0,0><<<dim3(MROWS/128, KDIM/128), 256>>>(
        xh, xl, nullptr, nullptr, nullptr, c1h, c1l, c1b, y1p);
    k_stats1<<<KDIM/8, 256>>>();
    k_mma<KDIM,EDIM,0,1><<<dim3(MROWS/128, 1), 256>>>(
        nullptr, nullptr, y1p, m1, i1, c2h, c2l, c2b, y2p);
    k_stats2<<<EDIM/8, 256>>>();
    k_mma<EDIM,EDIM,3,1><<<dim3(MROWS/128, 1), 256>>>(
        nullptr, nullptr, y2p, m2, i2, c3h, c3l, c3b, out);
}